// round 16
// baseline (speedup 1.0000x reference)
#include <cuda_runtime.h>
#include <cuda_fp16.h>
#include <math.h>
#include <stdint.h>

#define BATCH 32768
#define HID 256
#define NDOF 7
#define NTRIL 21
#define NHEAD 35   // 7 g + 7 Ld + 21 Lt

typedef __half fp16;

// ---------------- scratch (device globals; no allocation allowed) -------------
__device__ fp16  g_h0h [BATCH * HID];
__device__ fp16  g_h1h [BATCH * HID];
__device__ fp16  g_X2h [BATCH * HID];
__device__ fp16  g_sg0 [BATCH * HID];     // sigmoid(pre0) fp16
__device__ float g_sig1[BATCH * HID];
__device__ float g_sig2[BATCH * HID];
__device__ fp16  g_U0  [BATCH * HID];     // JVP chain
__device__ fp16  g_U1  [BATCH * HID];
__device__ fp16  g_U2  [BATCH * HID];
__device__ fp16  g_G2  [BATCH * HID];     // VJP chain
__device__ fp16  g_G1  [BATCH * HID];
__device__ fp16  g_G0t [(size_t)HID * BATCH];   // G0s TRANSPOSED [k][b]
__device__ float g_Yh  [(size_t)70 * BATCH];    // rows: 0..34 val | 35..69 JVP
__device__ fp16  g_W1h[HID * HID];
__device__ fp16  g_W1l[HID * HID];
__device__ fp16  g_W2h[HID * HID];
__device__ fp16  g_W2l[HID * HID];
__device__ fp16  g_W1t[HID * HID];        // W1^T (hi)
__device__ fp16  g_W2t[HID * HID];        // W2^T (hi)
__device__ fp16  g_WHh[64 * HID];         // padded head weights [64,256]
__device__ fp16  g_WHl[64 * HID];
__device__ fp16  g_WHt[HID * 64];         // WH^T [256,64] (hi)
__device__ float g_bH [64];

// ---------------- helpers ------------------------------------------------------
__device__ __forceinline__ float sp_f(float x) {
    return fmaxf(x, 0.0f) + log1pf(expf(-fabsf(x)));
}
__device__ __forceinline__ float sg_f(float x) {
    return 1.0f / (1.0f + expf(-x));
}
__device__ __forceinline__ void split_h(float x, fp16& h, fp16& l) {
    h = __float2half_rn(x);
    l = __float2half_rn(x - __half2float(h));
}
__device__ __forceinline__ void mma16816(float c[4], const uint32_t a[4],
                                         uint32_t b0, uint32_t b1) {
    asm volatile(
        "mma.sync.aligned.m16n8k16.row.col.f32.f16.f16.f32 "
        "{%0,%1,%2,%3}, {%4,%5,%6,%7}, {%8,%9}, {%0,%1,%2,%3};"
        : "+f"(c[0]), "+f"(c[1]), "+f"(c[2]), "+f"(c[3])
        : "r"(a[0]), "r"(a[1]), "r"(a[2]), "r"(a[3]), "r"(b0), "r"(b1));
}
__device__ __forceinline__ void ldsm4(uint32_t r[4], uint32_t addr) {
    asm volatile("ldmatrix.sync.aligned.m8n8.x4.shared.b16 {%0,%1,%2,%3}, [%4];"
                 : "=r"(r[0]), "=r"(r[1]), "=r"(r[2]), "=r"(r[3]) : "r"(addr));
}
__device__ __forceinline__ uint32_t smem_u32(const void* p) {
    uint32_t a;
    asm("{ .reg .u64 t; cvta.to.shared.u64 t, %1; cvt.u32.u64 %0, t; }"
        : "=r"(a) : "l"(p));
    return a;
}
__device__ __forceinline__ void cpa16(uint32_t s, const void* g) {
    asm volatile("cp.async.cg.shared.global [%0], [%1], 16;" :: "r"(s), "l"(g));
}
__device__ __forceinline__ void sts16(uint32_t s, fp16 a, fp16 b) {
    const __half2 v = __halves2half2(a, b);
    asm volatile("st.shared.b32 [%0], %1;" :: "r"(s), "r"(*(const uint32_t*)&v));
}

#define SMS 40
#define VA 10240u
#define VB 5120u
#define VSTG (VA + 2 * VB)    // 20480
#define VSM  (3 * VSTG)       // 61440 (3-stage)
#define TA 10240u
#define TB 5120u
#define TSTG (TA + TB)        // 15360
#define TSM  (3 * TSTG)       // 46080 (3-stage)

// ---------------- val_body: 2-term fp16 GEMM, 128x64, 3-stage ------------------
// MODE 0: h0 @ W1^T + b1 -> h1, sig1 | MODE 2: h1 @ W2^T + b2 -> X2, sig2
// MODE 4: X2 @ WH^T + bH -> Yh rows 0..34
template <int MODE>
__device__ __forceinline__ void val_body(const float* __restrict__ bias,
                                         int nblk, char* smraw)
{
    const uint32_t smb = smem_u32(smraw);
    const int tid  = threadIdx.x;
    const int warp = tid >> 5, lane = tid & 31;
    const int wm = (warp >> 1) * 32;
    const int wn = (warp & 1) * 32;
    const int g  = lane >> 2, t4 = lane & 3;
    const size_t m_base = (size_t)blockIdx.y * 128;
    const int    n_base = nblk * 64;

    const fp16 *Ap, *Bh, *Bl;
    if      (MODE == 0) { Ap = g_h0h; Bh = g_W1h; Bl = g_W1l; }
    else if (MODE == 2) { Ap = g_h1h; Bh = g_W2h; Bl = g_W2l; }
    else                { Ap = g_X2h; Bh = g_WHh; Bl = g_WHl; }

    const uint32_t a_off = (uint32_t)(((wm + (lane & 15)) * SMS) + ((lane >> 4) << 3)) * 2;
    const uint32_t b_off = (uint32_t)(((wn + ((lane >> 4) << 3) + (lane & 7)) * SMS)
                                      + (((lane >> 3) & 1) << 3)) * 2;

    float acc[2][4][4];
#pragma unroll
    for (int a = 0; a < 2; a++)
#pragma unroll
        for (int b = 0; b < 4; b++)
#pragma unroll
            for (int c = 0; c < 4; c++) acc[a][b][c] = 0.0f;

#define VP(STAGE, KT)                                                           \
    {                                                                           \
        const uint32_t sb = smb + (STAGE) * VSTG;                               \
        {   const int u = tid;                                                  \
            cpa16(sb + (uint32_t)((u >> 2) * 80 + (u & 3) * 16),                \
                  Ap + (m_base + (u >> 2)) * HID + (KT) + (u & 3) * 8); }       \
        {   const int u = tid + 256;                                            \
            cpa16(sb + (uint32_t)((u >> 2) * 80 + (u & 3) * 16),                \
                  Ap + (m_base + (u >> 2)) * HID + (KT) + (u & 3) * 8); }       \
        {   const int u = tid;                                                  \
            const uint32_t d = sb + VA + (uint32_t)((u >> 2) * 80 + (u & 3) * 16); \
            const size_t so = (size_t)(n_base + (u >> 2)) * HID + (KT) + (u & 3) * 8; \
            cpa16(d,      Bh + so);                                             \
            cpa16(d + VB, Bl + so); }                                           \
        asm volatile("cp.async.commit_group;");                                 \
    }

    VP(0, 0)
    VP(1, 32)

#pragma unroll
    for (int it = 0; it < 8; it++) {
        if (it < 7) asm volatile("cp.async.wait_group 1;");
        else        asm volatile("cp.async.wait_group 0;");
        __syncthreads();
        if (it + 2 < 8) {
            const int st = (it + 2) % 3;
            VP(st, (it + 2) * 32)
        }

        const uint32_t sb = smb + (it % 3) * VSTG;
#pragma unroll
        for (int ks = 0; ks < 2; ks++) {
            const uint32_t kso = ks * 32;
            uint32_t ah[2][4];
            ldsm4(ah[0], sb + a_off + kso);
            ldsm4(ah[1], sb + a_off + kso + 16 * SMS * 2);
#pragma unroll
            for (int njp = 0; njp < 2; njp++) {
                uint32_t bh[4], bl[4];
                ldsm4(bh, sb + VA + b_off + njp * (16 * SMS * 2) + kso);
                ldsm4(bl, sb + VA + VB + b_off + njp * (16 * SMS * 2) + kso);
#pragma unroll
                for (int mi = 0; mi < 2; mi++) {
#pragma unroll
                    for (int s = 0; s < 2; s++) {
                        float* C = acc[mi][njp * 2 + s];
                        mma16816(C, ah[mi], bh[2 * s], bh[2 * s + 1]);
                        mma16816(C, ah[mi], bl[2 * s], bl[2 * s + 1]);
                    }
                }
            }
        }
    }
#undef VP

#pragma unroll
    for (int mi = 0; mi < 2; mi++) {
#pragma unroll
        for (int half = 0; half < 2; half++) {
            const size_t m = m_base + wm + mi * 16 + g + half * 8;
#pragma unroll
            for (int nj = 0; nj < 4; nj++) {
                const int col = n_base + wn + nj * 8 + t4 * 2;
#pragma unroll
                for (int e = 0; e < 2; e++) {
                    const float v = acc[mi][nj][half * 2 + e];
                    const int cc = col + e;
                    if (MODE == 0) {
                        const float pre = v + bias[cc];
                        const size_t o = m * HID + cc;
                        g_h1h[o] = __float2half_rn(sp_f(pre));
                        g_sig1[o] = sg_f(pre);
                    } else if (MODE == 2) {
                        const float pre = v + bias[cc];
                        const size_t o = m * HID + cc;
                        g_X2h[o] = __float2half_rn(sp_f(pre));
                        g_sig2[o] = sg_f(pre);
                    } else {
                        if (cc < NHEAD)
                            g_Yh[(size_t)cc * BATCH + m] = v + g_bH[cc];
                    }
                }
            }
        }
    }
}

// ---------------- tan_body: 1-term fp16 GEMM, 128x64 tile, 3-stage -------------
// EPI 0: U0 @ W1^T  -> *sig1 -> U1     | EPI 1: U1 @ W2^T  -> *sig2 -> U2
// EPI 2: U2 @ WH^T  -> Yh 35..69       | EPI 3: seed(smem) @ WHt^T -> *sig2 -> G2
// EPI 4: G2 @ W2t^T -> *sig1 -> G1     | EPI 5: G1 @ W1t^T -> *sg0 -> G0t (transposed)
template <int EPI>
__device__ __forceinline__ void tan_body(int nblk, char* smraw,
                                         const float* __restrict__ qd_g)
{
    constexpr int KD  = (EPI == 3) ? 64 : 256;
    constexpr int NCH = KD / 32;

    const uint32_t smb = smem_u32(smraw);
    const int tid  = threadIdx.x;
    const int warp = tid >> 5, lane = tid & 31;
    const int wm = (warp >> 1) * 32;
    const int wn = (warp & 1) * 32;
    const int g  = lane >> 2, t4 = lane & 3;
    const size_t m_base = (size_t)blockIdx.y * 128;
    const int    n_base = nblk * 64;

    const fp16 *Ap, *Bp;
    if      (EPI == 0) { Ap = g_U0;  Bp = g_W1h; }
    else if (EPI == 1) { Ap = g_U1;  Bp = g_W2h; }
    else if (EPI == 2) { Ap = g_U2;  Bp = g_WHh; }
    else if (EPI == 3) { Ap = nullptr; Bp = g_WHt; }
    else if (EPI == 4) { Ap = g_G2;  Bp = g_W2t; }
    else               { Ap = g_G1;  Bp = g_W1t; }

    const uint32_t a_off = (uint32_t)(((wm + (lane & 15)) * SMS) + ((lane >> 4) << 3)) * 2;
    const uint32_t b_off = (uint32_t)(((wn + ((lane >> 4) << 3) + (lane & 7)) * SMS)
                                      + (((lane >> 3) & 1) << 3)) * 2;

    float acc[2][4][4];
#pragma unroll
    for (int a = 0; a < 2; a++)
#pragma unroll
        for (int b = 0; b < 4; b++)
#pragma unroll
            for (int c = 0; c < 4; c++) acc[a][b][c] = 0.0f;

    if (EPI == 3) {
        // ---- B loads for both K-chunks (WHt rows n_base..n_base+63, K=64) ----
#pragma unroll
        for (int st = 0; st < 2; st++) {
            const int u = tid;
            cpa16(smb + st * TSTG + TA + (uint32_t)((u >> 2) * 80 + (u & 3) * 16),
                  Bp + (size_t)(n_base + (u >> 2)) * 64 + st * 32 + (u & 3) * 8);
        }
        asm volatile("cp.async.commit_group;");

        // ---- seed A directly in smem: rows = samples, cols = head index -----
        if (tid < 128) {
            const size_t m = m_base + tid;
            const int R[21]  = {1,2,2,3,3,3,4,4,4,4,5,5,5,5,5,6,6,6,6,6,6};
            const int Cc[21] = {0,0,1,0,1,2,0,1,2,3,0,1,2,3,4,0,1,2,3,4,5};
            float qd[7], ldr[7];
#pragma unroll
            for (int i = 0; i < 7; i++) {
                qd[i]  = qd_g[m * 7 + i];
                ldr[i] = g_Yh[(size_t)(7 + i) * BATCH + m];
            }
            float L[28];
#pragma unroll
            for (int i = 0; i < 7; i++)
                L[i * (i + 1) / 2 + i] = sp_f(ldr[i]) + 1e-3f;
#pragma unroll
            for (int p = 0; p < 21; p++)
                L[R[p] * (R[p] + 1) / 2 + Cc[p]] =
                    g_Yh[(size_t)(14 + p) * BATCH + m];
            float a[7];
#pragma unroll
            for (int j = 0; j < 7; j++) {
                float s = 0.0f;
#pragma unroll
                for (int i = 0; i < 7; i++)
                    if (i >= j) s = fmaf(L[i * (i + 1) / 2 + j], qd[i], s);
                a[j] = s;
            }
            fp16 y[64];
#pragma unroll
            for (int r = 0; r < 64; r++) y[r] = __float2half_rn(0.0f);
#pragma unroll
            for (int i = 0; i < 7; i++)
                y[7 + i] = __float2half_rn(sg_f(ldr[i]) * qd[i] * a[i]);
#pragma unroll
            for (int p = 0; p < 21; p++)
                y[14 + p] = __float2half_rn(qd[R[p]] * a[Cc[p]]);
            const uint32_t rbase = smb + (uint32_t)tid * 80;
#pragma unroll
            for (int k2 = 0; k2 < 16; k2++)
                sts16(rbase + k2 * 4, y[2 * k2], y[2 * k2 + 1]);
#pragma unroll
            for (int k2 = 0; k2 < 16; k2++)
                sts16(rbase + TSTG + k2 * 4, y[32 + 2 * k2], y[32 + 2 * k2 + 1]);
        }
        asm volatile("cp.async.wait_group 0;");
        __syncthreads();

#pragma unroll
        for (int it = 0; it < 2; it++) {
            const uint32_t sb = smb + it * TSTG;
#pragma unroll
            for (int ks = 0; ks < 2; ks++) {
                const uint32_t kso = ks * 32;
                uint32_t ah[2][4];
                ldsm4(ah[0], sb + a_off + kso);
                ldsm4(ah[1], sb + a_off + kso + 16 * SMS * 2);
#pragma unroll
                for (int njp = 0; njp < 2; njp++) {
                    uint32_t bh[4];
                    ldsm4(bh, sb + TA + b_off + njp * (16 * SMS * 2) + kso);
#pragma unroll
                    for (int mi = 0; mi < 2; mi++) {
#pragma unroll
                        for (int s = 0; s < 2; s++)
                            mma16816(acc[mi][njp * 2 + s], ah[mi],
                                     bh[2 * s], bh[2 * s + 1]);
                    }
                }
            }
        }
    } else {

#define GP(STAGE, KT)                                                           \
    {                                                                           \
        const uint32_t sb = smb + (STAGE) * TSTG;                               \
        {   const int u = tid;                                                  \
            cpa16(sb + (uint32_t)((u >> 2) * 80 + (u & 3) * 16),                \
                  Ap + (m_base + (u >> 2)) * KD + (KT) + (u & 3) * 8); }        \
        {   const int u = tid + 256;                                            \
            cpa16(sb + (uint32_t)((u >> 2) * 80 + (u & 3) * 16),                \
                  Ap + (m_base + (u >> 2)) * KD + (KT) + (u & 3) * 8); }        \
        {   const int u = tid;                                                  \
            cpa16(sb + TA + (uint32_t)((u >> 2) * 80 + (u & 3) * 16),           \
                  Bp + (size_t)(n_base + (u >> 2)) * KD + (KT) + (u & 3) * 8); } \
        asm volatile("cp.async.commit_group;");                                 \
    }

        GP(0, 0)
        GP(1, 32)

#pragma unroll
        for (int it = 0; it < NCH; it++) {
            if (it < NCH - 1) asm volatile("cp.async.wait_group 1;");
            else              asm volatile("cp.async.wait_group 0;");
            __syncthreads();
            if (it + 2 < NCH) {
                const int st = (it + 2) % 3;
                GP(st, (it + 2) * 32)
            }

            const uint32_t sb = smb + (it % 3) * TSTG;
#pragma unroll
            for (int ks = 0; ks < 2; ks++) {
                const uint32_t kso = ks * 32;
                uint32_t ah[2][4];
                ldsm4(ah[0], sb + a_off + kso);
                ldsm4(ah[1], sb + a_off + kso + 16 * SMS * 2);
#pragma unroll
                for (int njp = 0; njp < 2; njp++) {
                    uint32_t bh[4];
                    ldsm4(bh, sb + TA + b_off + njp * (16 * SMS * 2) + kso);
#pragma unroll
                    for (int mi = 0; mi < 2; mi++) {
#pragma unroll
                        for (int s = 0; s < 2; s++)
                            mma16816(acc[mi][njp * 2 + s], ah[mi],
                                     bh[2 * s], bh[2 * s + 1]);
                    }
                }
            }
        }
#undef GP
    }

#pragma unroll
    for (int mi = 0; mi < 2; mi++) {
#pragma unroll
        for (int half = 0; half < 2; half++) {
            const size_t m = m_base + wm + mi * 16 + g + half * 8;
#pragma unroll
            for (int nj = 0; nj < 4; nj++) {
                const int col = wn + nj * 8 + t4 * 2;
#pragma unroll
                for (int e = 0; e < 2; e++) {
                    const float v = acc[mi][nj][half * 2 + e];
                    const int cc = n_base + col + e;
                    if (EPI == 0) {
                        const size_t o = m * HID + cc;
                        g_U1[o] = __float2half_rn(v * g_sig1[o]);
                    } else if (EPI == 1) {
                        const size_t o = m * HID + cc;
                        g_U2[o] = __float2half_rn(v * g_sig2[o]);
                    } else if (EPI == 2) {
                        if (cc < NHEAD) g_Yh[(size_t)(35 + cc) * BATCH + m] = v;
                    } else if (EPI == 3) {
                        const size_t o = m * HID + cc;
                        g_G2[o] = __float2half_rn(v * g_sig2[o]);
                    } else if (EPI == 4) {
                        const size_t o = m * HID + cc;
                        g_G1[o] = __float2half_rn(v * g_sig1[o]);
                    } else {
                        // EPI 5: transposed store for coalesced k_dyn reads
                        const float d = v * __half2float(g_sg0[m * HID + cc]);
                        g_G0t[(size_t)cc * BATCH + m] = __float2half_rn(d);
                    }
                }
            }
        }
    }
}

// ---------------- kernels wrapping the bodies ----------------------------------
__global__ __launch_bounds__(256, 3) void k_val0(const float* __restrict__ bias) {
    extern __shared__ char smraw[];
    val_body<0>(bias, blockIdx.x, smraw);
}
__global__ __launch_bounds__(256, 3) void k_fuseA(const float* __restrict__ bias) {
    extern __shared__ char smraw[];
    if (blockIdx.x < 4) val_body<2>(bias, blockIdx.x, smraw);
    else                tan_body<0>(blockIdx.x - 4, smraw, nullptr);
}
__global__ __launch_bounds__(256, 3) void k_fuseB() {
    extern __shared__ char smraw[];
    if (blockIdx.x < 4) tan_body<1>(blockIdx.x, smraw, nullptr);
    else                val_body<4>(nullptr, 0, smraw);
}
__global__ __launch_bounds__(256, 3) void k_fuseC(const float* __restrict__ qd) {
    extern __shared__ char smraw[];
    if (blockIdx.x < 4) tan_body<3>(blockIdx.x, smraw, qd);
    else                tan_body<2>(0, smraw, nullptr);
}
__global__ __launch_bounds__(256, 4) void k_g1()  { extern __shared__ char s[]; tan_body<4>(blockIdx.x, s, nullptr); }
__global__ __launch_bounds__(256, 4) void k_g0s() { extern __shared__ char s[]; tan_body<5>(blockIdx.x, s, nullptr); }

// ---------------- K0a: W1/W2 hi/lo split + transposes ---------------------------
__global__ __launch_bounds__(256) void k_wsplit(const float* __restrict__ W1,
                                                const float* __restrict__ W2)
{
    const int i = blockIdx.x * 256 + threadIdx.x;
    const int r = i >> 8, c = i & 255;
    split_h(W1[i], g_W1h[i], g_W1l[i]);
    split_h(W2[i], g_W2h[i], g_W2l[i]);
    g_W1t[c * HID + r] = __float2half_rn(W1[i]);
    g_W2t[c * HID + r] = __float2half_rn(W2[i]);
}

// ---------------- K0b: padded head weights (+ WHt, bias) ------------------------
__global__ __launch_bounds__(256) void k_whead(const float* __restrict__ Wg,
                                               const float* __restrict__ bg,
                                               const float* __restrict__ Wld,
                                               const float* __restrict__ bld,
                                               const float* __restrict__ Wlt,
                                               const float* __restrict__ blt)
{
    const int i = blockIdx.x * 256 + threadIdx.x;
    const int r = i >> 8, k = i & 255;
    float v = 0.0f;
    if      (r < 7)  v = Wg [r * HID + k];
    else if (r < 14) v = Wld[(r - 7) * HID + k];
    else if (r < 35) v = Wlt[(r - 14) * HID + k];
    split_h(v, g_WHh[i], g_WHl[i]);
    g_WHt[k * 64 + r] = __float2half_rn(v);
    if (i < 64) {
        float b = 0.0f;
        if      (i < 7)  b = bg [i];
        else if (i < 14) b = bld[i - 7];
        else if (i < 35) b = blt[i - 14];
        g_bH[i] = b;
    }
}

// ---------------- K1: layer0 values + JVP seed ---------------------------------
__global__ __launch_bounds__(256) void k_layer0(const float* __restrict__ q,
                                                const float* __restrict__ qd,
                                                const float* __restrict__ W0,
                                                const float* __restrict__ b0)
{
    __shared__ float qs[32][8], qds[32][8];
    const int j  = threadIdx.x;
    const int s0 = blockIdx.x * 32;
    for (int idx = threadIdx.x; idx < 32 * 7; idx += 256) {
        qs [idx / 7][idx % 7] = q [(s0 + idx / 7) * 7 + idx % 7];
        qds[idx / 7][idx % 7] = qd[(s0 + idx / 7) * 7 + idx % 7];
    }
    float w[7];
#pragma unroll
    for (int i = 0; i < 7; i++) w[i] = W0[j * 7 + i];
    const float bb = b0[j];
    __syncthreads();
    for (int s = 0; s < 32; s++) {
        float pre = bb, td = 0.0f;
#pragma unroll
        for (int i = 0; i < 7; i++) {
            pre = fmaf(w[i], qs[s][i], pre);
            td  = fmaf(w[i], qds[s][i], td);
        }
        const int b = s0 + s;
        const int off = b * HID + j;
        g_h0h[off] = __float2half_rn(sp_f(pre));
        const float sg = sg_f(pre);
        g_sg0[off] = __float2half_rn(sg);
        g_U0 [off] = __float2half_rn(sg * td);
    }
}

// ---------------- K8: per-sample dynamics (+ inlined svec GEMV) ----------------
#define POS(i, j) ((i) * ((i) + 1) / 2 + (j))

__global__ __launch_bounds__(128) void k_dyn(const float* __restrict__ qd_g,
                                             const float* __restrict__ qdd_g,
                                             const float* __restrict__ W0g,
                                             const float* __restrict__ fd,
                                             const float* __restrict__ fc,
                                             const float* __restrict__ fs,
                                             const float* __restrict__ fv,
                                             float* __restrict__ out)
{
    __shared__ float W0s[HID][7];
    for (int idx = threadIdx.x; idx < HID * 7; idx += 128)
        W0s[idx / 7][idx % 7] = W0g[idx];
    __syncthreads();

    const int b = blockIdx.x * 128 + threadIdx.x;
    if (b >= BATCH) return;
    const int R[21]  = {1,2,2,3,3,3,4,4,4,4,5,5,5,5,5,6,6,6,6,6,6};
    const int Cc[21] = {0,0,1,0,1,2,0,1,2,3,0,1,2,3,4,0,1,2,3,4,5};

#define YH(row) g_Yh[(size_t)(row) * BATCH + b]

    float qd[7], qdd[7], gv[7], ldr[7], sigd[7];
#pragma unroll
    for (int i = 0; i < 7; i++) {
        qd[i]  = qd_g [b * 7 + i];
        qdd[i] = qdd_g[b * 7 + i];
        gv[i]  = YH(i);
        ldr[i] = YH(7 + i);
    }

    float Lf[28];
#pragma unroll
    for (int i = 0; i < 7; i++) {
        Lf[POS(i, i)] = sp_f(ldr[i]) + 1e-3f;
        sigd[i] = sg_f(ldr[i]);
    }
#pragma unroll
    for (int p = 0; p < 21; p++) Lf[POS(R[p], Cc[p])] = YH(14 + p);

    float a[7];
#pragma unroll
    for (int j = 0; j < 7; j++) {
        float s = 0.0f;
#pragma unroll
        for (int i = 0; i < 7; i++) if (i >= j) s = fmaf(Lf[POS(i, j)], qd[i], s);
        a[j] = s;
    }

    float Ldt[28];
#pragma unroll
    for (int i = 0; i < 7; i++) Ldt[POS(i, i)] = sigd[i] * YH(35 + 7 + i);
#pragma unroll
    for (int p = 0; p < 21; p++) Ldt[POS(R[p], Cc[p])] = YH(35 + 14 + p);
#undef YH

    // svec = 2 * G0s[b,:] @ W0   (coalesced G0t reads, W0 broadcast from smem)
    float svec[7];
#pragma unroll
    for (int i = 0; i < 7; i++) svec[i] = 0.0f;
    for (int k = 0; k < HID; k++) {
        const float gk = __half2float(g_G0t[(size_t)k * BATCH + b]);
#pragma unroll
        for (int c = 0; c < 7; c++) svec[c] = fmaf(gk, W0s[k][c], svec[c]);
    }
#pragma unroll
    for (int i = 0; i < 7; i++) svec[i] *= 2.0f;

    float b2[7];
#pragma unroll
    for (int j = 0; j < 7; j++) {
        float s = 0.0f;
#pragma unroll
        for (int i = 0; i < 7; i++) if (i >= j) s = fmaf(Ldt[POS(i, j)], qd[i], s);
        b2[j] = s;
    }

    float cor[7];
#pragma unroll
    for (int i = 0; i < 7; i++) {
        float s = 0.0f;
#pragma unroll
        for (int j = 0; j < 7; j++) if (j <= i) s = fmaf(Lf[POS(i, j)], b2[j], s);
#pragma unroll
        for (int j = 0; j < 7; j++) if (j <= i) s = fmaf(Ldt[POS(i, j)], a[j], s);
        cor[i] = s - 0.5f * svec[i];
    }

    float Hmf[28];
#pragma unroll
    for (int i = 0; i < 7; i++)
#pragma unroll
        for (int k = 0; k < 7; k++) if (k <= i) {
            float s = 0.0f;
#pragma unroll
            for (int j = 0; j < 7; j++) if (j <= k)
                s = fmaf(Lf[POS(i, j)], Lf[POS(k, j)], s);
            Hmf[POS(i, k)] = s;
        }

    float fric[7];
#pragma unroll
    for (int i = 0; i < 7; i++) {
        const float fvc = fmaxf(fv[i], 1e-3f);
        fric[i] = (fc[i] + fs[i] * expf(-qd[i] * qd[i] / fvc)) *
                      tanhf(100.0f * qd[i]) + fd[i] * qd[i];
    }

    float tau[7];
#pragma unroll
    for (int i = 0; i < 7; i++) {
        float s = 0.0f;
#pragma unroll
        for (int k = 0; k < 7; k++) {
            const float h = (k <= i) ? Hmf[POS(i, k)] : Hmf[POS(k, i)];
            s = fmaf(h, qdd[k], s);
        }
        tau[i] = s + cor[i] + gv[i] + fric[i];
    }

    const int Bc = BATCH;
#pragma unroll
    for (int i = 0; i < 7; i++) out[b * 7 + i] = tau[i];
#pragma unroll
    for (int i = 0; i < 7; i++)
#pragma unroll
        for (int k = 0; k < 7; k++)
            out[7 * Bc + b * 49 + i * 7 + k] =
                (k <= i) ? Hmf[POS(i, k)] : Hmf[POS(k, i)];
#pragma unroll
    for (int i = 0; i < 7; i++) out[56 * Bc + b * 7 + i] = cor[i];
#pragma unroll
    for (int i = 0; i < 7; i++) out[63 * Bc + b * 7 + i] = gv[i];
#pragma unroll
    for (int i = 0; i < 7; i++) out[70 * Bc + b * 7 + i] = fric[i];
#pragma unroll
    for (int i = 0; i < 7; i++) out[77 * Bc + b * 7 + i] = ldr[i];
}

// ---------------- launch --------------------------------------------------------
extern "C" void kernel_launch(void* const* d_in, const int* in_sizes, int n_in,
                              void* d_out, int out_size)
{
    (void)in_sizes; (void)n_in; (void)out_size;
    const float* q   = (const float*)d_in[0];
    const float* qd  = (const float*)d_in[1];
    const float* qdd = (const float*)d_in[2];
    const float* W0  = (const float*)d_in[3];
    const float* b0  = (const float*)d_in[4];
    const float* W1  = (const float*)d_in[5];
    const float* b1  = (const float*)d_in[6];
    const float* W2  = (const float*)d_in[7];
    const float* b2  = (const float*)d_in[8];
    const float* Wg  = (const float*)d_in[9];
    const float* bg  = (const float*)d_in[10];
    const float* Wld = (const float*)d_in[11];
    const float* bld = (const float*)d_in[12];
    const float* Wlt = (const float*)d_in[13];
    const float* blt = (const float*)d_in[14];
    const float* fd  = (const float*)d_in[15];
    const float* fc  = (const float*)d_in[16];
    const float* fs  = (const float*)d_in[17];
    const float* fv  = (const float*)d_in[18];
    float* out = (float*)d_out;

    cudaFuncSetAttribute(k_val0,  cudaFuncAttributeMaxDynamicSharedMemorySize, VSM);
    cudaFuncSetAttribute(k_fuseA, cudaFuncAttributeMaxDynamicSharedMemorySize, VSM);
    cudaFuncSetAttribute(k_fuseB, cudaFuncAttributeMaxDynamicSharedMemorySize, VSM);
    cudaFuncSetAttribute(k_fuseC, cudaFuncAttributeMaxDynamicSharedMemorySize, TSM);
    cudaFuncSetAttribute(k_g1,    cudaFuncAttributeMaxDynamicSharedMemorySize, TSM);
    cudaFuncSetAttribute(k_g0s,   cudaFuncAttributeMaxDynamicSharedMemorySize, TSM);

    k_wsplit<<<HID * HID / 256, 256>>>(W1, W2);
    k_whead<<<64, 256>>>(Wg, bg, Wld, bld, Wlt, blt);
    k_layer0<<<BATCH / 32, 256>>>(q, qd, W0, b0);            // h0, sg0, U0
    k_val0 <<<dim3(4, BATCH / 128), 256, VSM>>>(b1);         // h1, sig1
    k_fuseA<<<dim3(8, BATCH / 128), 256, VSM>>>(b2);         // X2,sig2 || U1
    k_fuseB<<<dim3(5, BATCH / 128), 256, VSM>>>();           // U2 || Yh 0..34
    k_fuseC<<<dim3(5, BATCH / 128), 256, TSM>>>(qd);         // G2(seeded) || Yh 35..69
    k_g1   <<<dim3(4, BATCH / 128), 256, TSM>>>();           // G1
    k_g0s  <<<dim3(4, BATCH / 128), 256, TSM>>>();           // G0t (transposed)
    k_dyn  <<<(BATCH + 127) / 128, 128>>>(qd, qdd, W0, fd, fc, fs, fv, out);
}

// round 17
// speedup vs baseline: 1.0227x; 1.0227x over previous
#include <cuda_runtime.h>
#include <cuda_fp16.h>
#include <math.h>
#include <stdint.h>

#define BATCH 32768
#define HID 256
#define NDOF 7
#define NTRIL 21
#define NHEAD 35   // 7 g + 7 Ld + 21 Lt

typedef __half fp16;

// ---------------- scratch (device globals; no allocation allowed) -------------
__device__ fp16  g_h0h [BATCH * HID];
__device__ fp16  g_h1h [BATCH * HID];
__device__ fp16  g_X2h [BATCH * HID];
__device__ fp16  g_sg0 [BATCH * HID];     // sigmoid(pre0) fp16
__device__ float g_sig1[BATCH * HID];
__device__ float g_sig2[BATCH * HID];
__device__ fp16  g_U0  [BATCH * HID];     // JVP chain
__device__ fp16  g_U1  [BATCH * HID];
__device__ fp16  g_U2  [BATCH * HID];
__device__ fp16  g_G2  [BATCH * HID];     // VJP chain
__device__ fp16  g_G1  [BATCH * HID];
__device__ fp16  g_G0s [BATCH * HID];
__device__ float g_Yh  [(size_t)77 * BATCH];  // rows: 0..34 val | 35..69 JVP | 70..76 svec
__device__ fp16  g_W1h[HID * HID];
__device__ fp16  g_W1l[HID * HID];
__device__ fp16  g_W2h[HID * HID];
__device__ fp16  g_W2l[HID * HID];
__device__ fp16  g_W1t[HID * HID];        // W1^T (hi)
__device__ fp16  g_W2t[HID * HID];        // W2^T (hi)
__device__ fp16  g_WHh[64 * HID];         // padded head weights [64,256]
__device__ fp16  g_WHl[64 * HID];
__device__ fp16  g_WHt[HID * 64];         // WH^T [256,64] (hi)
__device__ fp16  g_W0t[64 * HID];         // rows 0..6 = 2*W0^T, rest 0
__device__ float g_bH [64];

// ---------------- helpers ------------------------------------------------------
__device__ __forceinline__ float sp_f(float x) {
    return fmaxf(x, 0.0f) + log1pf(expf(-fabsf(x)));
}
__device__ __forceinline__ float sg_f(float x) {
    return 1.0f / (1.0f + expf(-x));
}
__device__ __forceinline__ void split_h(float x, fp16& h, fp16& l) {
    h = __float2half_rn(x);
    l = __float2half_rn(x - __half2float(h));
}
__device__ __forceinline__ void mma16816(float c[4], const uint32_t a[4],
                                         uint32_t b0, uint32_t b1) {
    asm volatile(
        "mma.sync.aligned.m16n8k16.row.col.f32.f16.f16.f32 "
        "{%0,%1,%2,%3}, {%4,%5,%6,%7}, {%8,%9}, {%0,%1,%2,%3};"
        : "+f"(c[0]), "+f"(c[1]), "+f"(c[2]), "+f"(c[3])
        : "r"(a[0]), "r"(a[1]), "r"(a[2]), "r"(a[3]), "r"(b0), "r"(b1));
}
__device__ __forceinline__ void ldsm4(uint32_t r[4], uint32_t addr) {
    asm volatile("ldmatrix.sync.aligned.m8n8.x4.shared.b16 {%0,%1,%2,%3}, [%4];"
                 : "=r"(r[0]), "=r"(r[1]), "=r"(r[2]), "=r"(r[3]) : "r"(addr));
}
__device__ __forceinline__ uint32_t smem_u32(const void* p) {
    uint32_t a;
    asm("{ .reg .u64 t; cvta.to.shared.u64 t, %1; cvt.u32.u64 %0, t; }"
        : "=r"(a) : "l"(p));
    return a;
}
__device__ __forceinline__ void cpa16(uint32_t s, const void* g) {
    asm volatile("cp.async.cg.shared.global [%0], [%1], 16;" :: "r"(s), "l"(g));
}
__device__ __forceinline__ void sts16(uint32_t s, fp16 a, fp16 b) {
    const __half2 v = __halves2half2(a, b);
    asm volatile("st.shared.b32 [%0], %1;" :: "r"(s), "r"(*(const uint32_t*)&v));
}

#define SMS 40
#define VA 10240u
#define VB 5120u
#define VSTG (VA + 2 * VB)    // 20480
#define VSM  (3 * VSTG)       // 61440
#define TA 10240u
#define TB 5120u
#define TSTG (TA + TB)        // 15360
#define TSM  (3 * TSTG)       // 46080

// ---------------- val_body: 2-term fp16 GEMM (A-hi x (Bh+Bl)), 128x64 ----------
// MODE 0: h0 @ W1^T + b1 -> h1, sig1 | MODE 2: h1 @ W2^T + b2 -> X2, sig2
// MODE 4: X2 @ WH^T + bH -> Yh rows 0..34
template <int MODE>
__device__ __forceinline__ void val_body(const float* __restrict__ bias,
                                         int nblk, char* smraw)
{
    const uint32_t smb = smem_u32(smraw);
    const int tid  = threadIdx.x;
    const int warp = tid >> 5, lane = tid & 31;
    const int wm = (warp >> 1) * 32;
    const int wn = (warp & 1) * 32;
    const int g  = lane >> 2, t4 = lane & 3;
    const size_t m_base = (size_t)blockIdx.y * 128;
    const int    n_base = nblk * 64;

    const fp16 *Ap, *Bh, *Bl;
    if      (MODE == 0) { Ap = g_h0h; Bh = g_W1h; Bl = g_W1l; }
    else if (MODE == 2) { Ap = g_h1h; Bh = g_W2h; Bl = g_W2l; }
    else                { Ap = g_X2h; Bh = g_WHh; Bl = g_WHl; }

    const uint32_t a_off = (uint32_t)(((wm + (lane & 15)) * SMS) + ((lane >> 4) << 3)) * 2;
    const uint32_t b_off = (uint32_t)(((wn + ((lane >> 4) << 3) + (lane & 7)) * SMS)
                                      + (((lane >> 3) & 1) << 3)) * 2;

    float acc[2][4][4];
#pragma unroll
    for (int a = 0; a < 2; a++)
#pragma unroll
        for (int b = 0; b < 4; b++)
#pragma unroll
            for (int c = 0; c < 4; c++) acc[a][b][c] = 0.0f;

#define VP(STAGE, KT)                                                           \
    {                                                                           \
        const uint32_t sb = smb + (STAGE) * VSTG;                               \
        {   const int u = tid;                                                  \
            cpa16(sb + (uint32_t)((u >> 2) * 80 + (u & 3) * 16),                \
                  Ap + (m_base + (u >> 2)) * HID + (KT) + (u & 3) * 8); }       \
        {   const int u = tid + 256;                                            \
            cpa16(sb + (uint32_t)((u >> 2) * 80 + (u & 3) * 16),                \
                  Ap + (m_base + (u >> 2)) * HID + (KT) + (u & 3) * 8); }       \
        {   const int u = tid;                                                  \
            const uint32_t d = sb + VA + (uint32_t)((u >> 2) * 80 + (u & 3) * 16); \
            const size_t so = (size_t)(n_base + (u >> 2)) * HID + (KT) + (u & 3) * 8; \
            cpa16(d,      Bh + so);                                             \
            cpa16(d + VB, Bl + so); }                                           \
        asm volatile("cp.async.commit_group;");                                 \
    }

    VP(0, 0)
    VP(1, 32)

#pragma unroll
    for (int it = 0; it < 8; it++) {
        if (it < 7) asm volatile("cp.async.wait_group 1;");
        else        asm volatile("cp.async.wait_group 0;");
        __syncthreads();
        if (it + 2 < 8) {
            const int st = (it + 2) % 3;
            VP(st, (it + 2) * 32)
        }

        const uint32_t sb = smb + (it % 3) * VSTG;
#pragma unroll
        for (int ks = 0; ks < 2; ks++) {
            const uint32_t kso = ks * 32;
            uint32_t ah[2][4];
            ldsm4(ah[0], sb + a_off + kso);
            ldsm4(ah[1], sb + a_off + kso + 16 * SMS * 2);
#pragma unroll
            for (int njp = 0; njp < 2; njp++) {
                uint32_t bh[4], bl[4];
                ldsm4(bh, sb + VA + b_off + njp * (16 * SMS * 2) + kso);
                ldsm4(bl, sb + VA + VB + b_off + njp * (16 * SMS * 2) + kso);
#pragma unroll
                for (int mi = 0; mi < 2; mi++) {
#pragma unroll
                    for (int s = 0; s < 2; s++) {
                        float* C = acc[mi][njp * 2 + s];
                        mma16816(C, ah[mi], bh[2 * s], bh[2 * s + 1]);
                        mma16816(C, ah[mi], bl[2 * s], bl[2 * s + 1]);
                    }
                }
            }
        }
    }
#undef VP

#pragma unroll
    for (int mi = 0; mi < 2; mi++) {
#pragma unroll
        for (int half = 0; half < 2; half++) {
            const size_t m = m_base + wm + mi * 16 + g + half * 8;
#pragma unroll
            for (int nj = 0; nj < 4; nj++) {
                const int col = n_base + wn + nj * 8 + t4 * 2;
#pragma unroll
                for (int e = 0; e < 2; e++) {
                    const float v = acc[mi][nj][half * 2 + e];
                    const int cc = col + e;
                    if (MODE == 0) {
                        const float pre = v + bias[cc];
                        const size_t o = m * HID + cc;
                        g_h1h[o] = __float2half_rn(sp_f(pre));
                        g_sig1[o] = sg_f(pre);
                    } else if (MODE == 2) {
                        const float pre = v + bias[cc];
                        const size_t o = m * HID + cc;
                        g_X2h[o] = __float2half_rn(sp_f(pre));
                        g_sig2[o] = sg_f(pre);
                    } else {
                        if (cc < NHEAD)
                            g_Yh[(size_t)cc * BATCH + m] = v + g_bH[cc];
                    }
                }
            }
        }
    }
}

// ---------------- tan_body: 1-term fp16 GEMM, 128x64 tile ----------------------
// EPI 0: U0 @ W1^T  -> *sig1 -> U1     | EPI 1: U1 @ W2^T  -> *sig2 -> U2
// EPI 2: U2 @ WH^T  -> Yh 35..69       | EPI 3: seed(smem) @ WHt^T -> *sig2 -> G2
// EPI 4: G2 @ W2t^T -> *sig1 -> G1     | EPI 5: G1 @ W1t^T -> *sg0 -> G0s
// EPI 6: G0s @ W0t^T -> Yh 70..76
template <int EPI>
__device__ __forceinline__ void tan_body(int nblk, char* smraw,
                                         const float* __restrict__ qd_g)
{
    constexpr int KD  = (EPI == 3) ? 64 : 256;
    constexpr int NCH = KD / 32;

    const uint32_t smb = smem_u32(smraw);
    const int tid  = threadIdx.x;
    const int warp = tid >> 5, lane = tid & 31;
    const int wm = (warp >> 1) * 32;
    const int wn = (warp & 1) * 32;
    const int g  = lane >> 2, t4 = lane & 3;
    const size_t m_base = (size_t)blockIdx.y * 128;
    const int    n_base = nblk * 64;

    const fp16 *Ap, *Bp;
    if      (EPI == 0) { Ap = g_U0;  Bp = g_W1h; }
    else if (EPI == 1) { Ap = g_U1;  Bp = g_W2h; }
    else if (EPI == 2) { Ap = g_U2;  Bp = g_WHh; }
    else if (EPI == 3) { Ap = nullptr; Bp = g_WHt; }
    else if (EPI == 4) { Ap = g_G2;  Bp = g_W2t; }
    else if (EPI == 5) { Ap = g_G1;  Bp = g_W1t; }
    else               { Ap = g_G0s; Bp = g_W0t; }

    const uint32_t a_off = (uint32_t)(((wm + (lane & 15)) * SMS) + ((lane >> 4) << 3)) * 2;
    const uint32_t b_off = (uint32_t)(((wn + ((lane >> 4) << 3) + (lane & 7)) * SMS)
                                      + (((lane >> 3) & 1) << 3)) * 2;

    float acc[2][4][4];
#pragma unroll
    for (int a = 0; a < 2; a++)
#pragma unroll
        for (int b = 0; b < 4; b++)
#pragma unroll
            for (int c = 0; c < 4; c++) acc[a][b][c] = 0.0f;

    if (EPI == 3) {
        // ---- B loads for both K-chunks (WHt rows n_base..n_base+63, K=64) ----
#pragma unroll
        for (int st = 0; st < 2; st++) {
            const int u = tid;
            cpa16(smb + st * TSTG + TA + (uint32_t)((u >> 2) * 80 + (u & 3) * 16),
                  Bp + (size_t)(n_base + (u >> 2)) * 64 + st * 32 + (u & 3) * 8);
        }
        asm volatile("cp.async.commit_group;");

        // ---- seed A directly in smem: rows = samples, cols = head index -----
        if (tid < 128) {
            const size_t m = m_base + tid;
            const int R[21]  = {1,2,2,3,3,3,4,4,4,4,5,5,5,5,5,6,6,6,6,6,6};
            const int Cc[21] = {0,0,1,0,1,2,0,1,2,3,0,1,2,3,4,0,1,2,3,4,5};
            float qd[7], ldr[7];
#pragma unroll
            for (int i = 0; i < 7; i++) {
                qd[i]  = qd_g[m * 7 + i];
                ldr[i] = g_Yh[(size_t)(7 + i) * BATCH + m];
            }
            float L[28];
#pragma unroll
            for (int i = 0; i < 7; i++)
                L[i * (i + 1) / 2 + i] = sp_f(ldr[i]) + 1e-3f;
#pragma unroll
            for (int p = 0; p < 21; p++)
                L[R[p] * (R[p] + 1) / 2 + Cc[p]] =
                    g_Yh[(size_t)(14 + p) * BATCH + m];
            float a[7];
#pragma unroll
            for (int j = 0; j < 7; j++) {
                float s = 0.0f;
#pragma unroll
                for (int i = 0; i < 7; i++)
                    if (i >= j) s = fmaf(L[i * (i + 1) / 2 + j], qd[i], s);
                a[j] = s;
            }
            fp16 y[64];
#pragma unroll
            for (int r = 0; r < 64; r++) y[r] = __float2half_rn(0.0f);
#pragma unroll
            for (int i = 0; i < 7; i++)
                y[7 + i] = __float2half_rn(sg_f(ldr[i]) * qd[i] * a[i]);
#pragma unroll
            for (int p = 0; p < 21; p++)
                y[14 + p] = __float2half_rn(qd[R[p]] * a[Cc[p]]);
            const uint32_t rbase = smb + (uint32_t)tid * 80;
#pragma unroll
            for (int k2 = 0; k2 < 16; k2++)
                sts16(rbase + k2 * 4, y[2 * k2], y[2 * k2 + 1]);
#pragma unroll
            for (int k2 = 0; k2 < 16; k2++)
                sts16(rbase + TSTG + k2 * 4, y[32 + 2 * k2], y[32 + 2 * k2 + 1]);
        }
        asm volatile("cp.async.wait_group 0;");
        __syncthreads();

#pragma unroll
        for (int it = 0; it < 2; it++) {
            const uint32_t sb = smb + it * TSTG;
#pragma unroll
            for (int ks = 0; ks < 2; ks++) {
                const uint32_t kso = ks * 32;
                uint32_t ah[2][4];
                ldsm4(ah[0], sb + a_off + kso);
                ldsm4(ah[1], sb + a_off + kso + 16 * SMS * 2);
#pragma unroll
                for (int njp = 0; njp < 2; njp++) {
                    uint32_t bh[4];
                    ldsm4(bh, sb + TA + b_off + njp * (16 * SMS * 2) + kso);
#pragma unroll
                    for (int mi = 0; mi < 2; mi++) {
#pragma unroll
                        for (int s = 0; s < 2; s++)
                            mma16816(acc[mi][njp * 2 + s], ah[mi],
                                     bh[2 * s], bh[2 * s + 1]);
                    }
                }
            }
        }
    } else {

#define GP(STAGE, KT)                                                           \
    {                                                                           \
        const uint32_t sb = smb + (STAGE) * TSTG;                               \
        {   const int u = tid;                                                  \
            cpa16(sb + (uint32_t)((u >> 2) * 80 + (u & 3) * 16),                \
                  Ap + (m_base + (u >> 2)) * KD + (KT) + (u & 3) * 8); }        \
        {   const int u = tid + 256;                                            \
            cpa16(sb + (uint32_t)((u >> 2) * 80 + (u & 3) * 16),                \
                  Ap + (m_base + (u >> 2)) * KD + (KT) + (u & 3) * 8); }        \
        {   const int u = tid;                                                  \
            cpa16(sb + TA + (uint32_t)((u >> 2) * 80 + (u & 3) * 16),           \
                  Bp + (size_t)(n_base + (u >> 2)) * KD + (KT) + (u & 3) * 8); } \
        asm volatile("cp.async.commit_group;");                                 \
    }

        GP(0, 0)
        GP(1, 32)

#pragma unroll
        for (int it = 0; it < NCH; it++) {
            if (it < NCH - 1) asm volatile("cp.async.wait_group 1;");
            else              asm volatile("cp.async.wait_group 0;");
            __syncthreads();
            if (it + 2 < NCH) {
                const int st = (it + 2) % 3;
                GP(st, (it + 2) * 32)
            }

            const uint32_t sb = smb + (it % 3) * TSTG;
#pragma unroll
            for (int ks = 0; ks < 2; ks++) {
                const uint32_t kso = ks * 32;
                uint32_t ah[2][4];
                ldsm4(ah[0], sb + a_off + kso);
                ldsm4(ah[1], sb + a_off + kso + 16 * SMS * 2);
#pragma unroll
                for (int njp = 0; njp < 2; njp++) {
                    uint32_t bh[4];
                    ldsm4(bh, sb + TA + b_off + njp * (16 * SMS * 2) + kso);
#pragma unroll
                    for (int mi = 0; mi < 2; mi++) {
#pragma unroll
                        for (int s = 0; s < 2; s++)
                            mma16816(acc[mi][njp * 2 + s], ah[mi],
                                     bh[2 * s], bh[2 * s + 1]);
                    }
                }
            }
        }
#undef GP
    }

#pragma unroll
    for (int mi = 0; mi < 2; mi++) {
#pragma unroll
        for (int half = 0; half < 2; half++) {
            const size_t m = m_base + wm + mi * 16 + g + half * 8;
#pragma unroll
            for (int nj = 0; nj < 4; nj++) {
                const int col = wn + nj * 8 + t4 * 2;
#pragma unroll
                for (int e = 0; e < 2; e++) {
                    const float v = acc[mi][nj][half * 2 + e];
                    const int cc = n_base + col + e;
                    if (EPI == 0) {
                        const size_t o = m * HID + cc;
                        g_U1[o] = __float2half_rn(v * g_sig1[o]);
                    } else if (EPI == 1) {
                        const size_t o = m * HID + cc;
                        g_U2[o] = __float2half_rn(v * g_sig2[o]);
                    } else if (EPI == 2) {
                        if (cc < NHEAD) g_Yh[(size_t)(35 + cc) * BATCH + m] = v;
                    } else if (EPI == 3) {
                        const size_t o = m * HID + cc;
                        g_G2[o] = __float2half_rn(v * g_sig2[o]);
                    } else if (EPI == 4) {
                        const size_t o = m * HID + cc;
                        g_G1[o] = __float2half_rn(v * g_sig1[o]);
                    } else if (EPI == 5) {
                        const size_t o = m * HID + cc;
                        g_G0s[o] = __float2half_rn(v * __half2float(g_sg0[o]));
                    } else {
                        if (cc < 7) g_Yh[(size_t)(70 + cc) * BATCH + m] = v;
                    }
                }
            }
        }
    }
}

// ---------------- kernels wrapping the bodies ----------------------------------
__global__ __launch_bounds__(256, 3) void k_val0(const float* __restrict__ bias) {
    extern __shared__ char smraw[];
    val_body<0>(bias, blockIdx.x, smraw);
}
__global__ __launch_bounds__(256, 3) void k_fuseA(const float* __restrict__ bias) {
    extern __shared__ char smraw[];
    if (blockIdx.x < 4) val_body<2>(bias, blockIdx.x, smraw);
    else                tan_body<0>(blockIdx.x - 4, smraw, nullptr);
}
__global__ __launch_bounds__(256, 3) void k_fuseB() {
    extern __shared__ char smraw[];
    if (blockIdx.x < 4) tan_body<1>(blockIdx.x, smraw, nullptr);
    else                val_body<4>(nullptr, 0, smraw);
}
__global__ __launch_bounds__(256, 3) void k_fuseC(const float* __restrict__ qd) {
    extern __shared__ char smraw[];
    if (blockIdx.x < 4) tan_body<3>(blockIdx.x, smraw, qd);
    else                tan_body<2>(0, smraw, nullptr);
}
__global__ __launch_bounds__(256, 4) void k_g1()  { extern __shared__ char s[]; tan_body<4>(blockIdx.x, s, nullptr); }
__global__ __launch_bounds__(256, 4) void k_g0s() { extern __shared__ char s[]; tan_body<5>(blockIdx.x, s, nullptr); }
__global__ __launch_bounds__(256, 4) void k_sv()  { extern __shared__ char s[]; tan_body<6>(0, s, nullptr); }

// ---------------- k_prep: fused (layer0 | wsplit | whead) ----------------------
// blocks 0..1023: layer0 ; 1024..1279: W1/W2 split+transpose ; 1280..1343: heads
__global__ __launch_bounds__(256) void k_prep(const float* __restrict__ q,
                                              const float* __restrict__ qd,
                                              const float* __restrict__ W0,
                                              const float* __restrict__ b0,
                                              const float* __restrict__ W1,
                                              const float* __restrict__ W2,
                                              const float* __restrict__ Wg,
                                              const float* __restrict__ bg,
                                              const float* __restrict__ Wld,
                                              const float* __restrict__ bld,
                                              const float* __restrict__ Wlt,
                                              const float* __restrict__ blt)
{
    const int bx = blockIdx.x;
    if (bx < 1024) {
        // ---- layer0: values + JVP seed ----
        __shared__ float qs[32][8], qds[32][8];
        const int j  = threadIdx.x;
        const int s0 = bx * 32;
        for (int idx = threadIdx.x; idx < 32 * 7; idx += 256) {
            qs [idx / 7][idx % 7] = q [(s0 + idx / 7) * 7 + idx % 7];
            qds[idx / 7][idx % 7] = qd[(s0 + idx / 7) * 7 + idx % 7];
        }
        float w[7];
#pragma unroll
        for (int i = 0; i < 7; i++) w[i] = W0[j * 7 + i];
        const float bb = b0[j];
        __syncthreads();
        for (int s = 0; s < 32; s++) {
            float pre = bb, td = 0.0f;
#pragma unroll
            for (int i = 0; i < 7; i++) {
                pre = fmaf(w[i], qs[s][i], pre);
                td  = fmaf(w[i], qds[s][i], td);
            }
            const int b = s0 + s;
            const int off = b * HID + j;
            g_h0h[off] = __float2half_rn(sp_f(pre));
            const float sg = sg_f(pre);
            g_sg0[off] = __float2half_rn(sg);
            g_U0 [off] = __float2half_rn(sg * td);
        }
    } else if (bx < 1280) {
        // ---- W1/W2 hi/lo split + transposes ----
        const int i = (bx - 1024) * 256 + threadIdx.x;
        const int r = i >> 8, c = i & 255;
        split_h(W1[i], g_W1h[i], g_W1l[i]);
        split_h(W2[i], g_W2h[i], g_W2l[i]);
        g_W1t[c * HID + r] = __float2half_rn(W1[i]);
        g_W2t[c * HID + r] = __float2half_rn(W2[i]);
    } else {
        // ---- padded head weights + WHt + W0t + bias ----
        const int i = (bx - 1280) * 256 + threadIdx.x;
        const int r = i >> 8, k = i & 255;
        float v = 0.0f;
        if      (r < 7)  v = Wg [r * HID + k];
        else if (r < 14) v = Wld[(r - 7) * HID + k];
        else if (r < 35) v = Wlt[(r - 14) * HID + k];
        split_h(v, g_WHh[i], g_WHl[i]);
        g_WHt[k * 64 + r] = __float2half_rn(v);
        g_W0t[i] = __float2half_rn((r < 7) ? 2.0f * W0[k * 7 + r] : 0.0f);
        if (i < 64) {
            float b = 0.0f;
            if      (i < 7)  b = bg [i];
            else if (i < 14) b = bld[i - 7];
            else if (i < 35) b = blt[i - 14];
            g_bH[i] = b;
        }
    }
}

// ---------------- K8: per-sample dynamics --------------------------------------
#define POS(i, j) ((i) * ((i) + 1) / 2 + (j))

__global__ __launch_bounds__(128) void k_dyn(const float* __restrict__ qd_g,
                                             const float* __restrict__ qdd_g,
                                             const float* __restrict__ fd,
                                             const float* __restrict__ fc,
                                             const float* __restrict__ fs,
                                             const float* __restrict__ fv,
                                             float* __restrict__ out)
{
    const int b = blockIdx.x * 128 + threadIdx.x;
    if (b >= BATCH) return;
    const int R[21]  = {1,2,2,3,3,3,4,4,4,4,5,5,5,5,5,6,6,6,6,6,6};
    const int Cc[21] = {0,0,1,0,1,2,0,1,2,3,0,1,2,3,4,0,1,2,3,4,5};

#define YH(row) g_Yh[(size_t)(row) * BATCH + b]

    float qd[7], qdd[7], gv[7], ldr[7], sigd[7];
#pragma unroll
    for (int i = 0; i < 7; i++) {
        qd[i]  = qd_g [b * 7 + i];
        qdd[i] = qdd_g[b * 7 + i];
        gv[i]  = YH(i);
        ldr[i] = YH(7 + i);
    }

    float Lf[28];
#pragma unroll
    for (int i = 0; i < 7; i++) {
        Lf[POS(i, i)] = sp_f(ldr[i]) + 1e-3f;
        sigd[i] = sg_f(ldr[i]);
    }
#pragma unroll
    for (int p = 0; p < 21; p++) Lf[POS(R[p], Cc[p])] = YH(14 + p);

    float a[7];
#pragma unroll
    for (int j = 0; j < 7; j++) {
        float s = 0.0f;
#pragma unroll
        for (int i = 0; i < 7; i++) if (i >= j) s = fmaf(Lf[POS(i, j)], qd[i], s);
        a[j] = s;
    }

    float Ldt[28];
#pragma unroll
    for (int i = 0; i < 7; i++) Ldt[POS(i, i)] = sigd[i] * YH(35 + 7 + i);
#pragma unroll
    for (int p = 0; p < 21; p++) Ldt[POS(R[p], Cc[p])] = YH(35 + 14 + p);

    float svec[7];
#pragma unroll
    for (int i = 0; i < 7; i++) svec[i] = YH(70 + i);

    float b2[7];
#pragma unroll
    for (int j = 0; j < 7; j++) {
        float s = 0.0f;
#pragma unroll
        for (int i = 0; i < 7; i++) if (i >= j) s = fmaf(Ldt[POS(i, j)], qd[i], s);
        b2[j] = s;
    }

    float cor[7];
#pragma unroll
    for (int i = 0; i < 7; i++) {
        float s = 0.0f;
#pragma unroll
        for (int j = 0; j < 7; j++) if (j <= i) s = fmaf(Lf[POS(i, j)], b2[j], s);
#pragma unroll
        for (int j = 0; j < 7; j++) if (j <= i) s = fmaf(Ldt[POS(i, j)], a[j], s);
        cor[i] = s - 0.5f * svec[i];
    }
#undef YH

    float Hmf[28];
#pragma unroll
    for (int i = 0; i < 7; i++)
#pragma unroll
        for (int k = 0; k < 7; k++) if (k <= i) {
            float s = 0.0f;
#pragma unroll
            for (int j = 0; j < 7; j++) if (j <= k)
                s = fmaf(Lf[POS(i, j)], Lf[POS(k, j)], s);
            Hmf[POS(i, k)] = s;
        }

    float fric[7];
#pragma unroll
    for (int i = 0; i < 7; i++) {
        const float fvc = fmaxf(fv[i], 1e-3f);
        fric[i] = (fc[i] + fs[i] * expf(-qd[i] * qd[i] / fvc)) *
                      tanhf(100.0f * qd[i]) + fd[i] * qd[i];
    }

    float tau[7];
#pragma unroll
    for (int i = 0; i < 7; i++) {
        float s = 0.0f;
#pragma unroll
        for (int k = 0; k < 7; k++) {
            const float h = (k <= i) ? Hmf[POS(i, k)] : Hmf[POS(k, i)];
            s = fmaf(h, qdd[k], s);
        }
        tau[i] = s + cor[i] + gv[i] + fric[i];
    }

    const int Bc = BATCH;
#pragma unroll
    for (int i = 0; i < 7; i++) out[b * 7 + i] = tau[i];
#pragma unroll
    for (int i = 0; i < 7; i++)
#pragma unroll
        for (int k = 0; k < 7; k++)
            out[7 * Bc + b * 49 + i * 7 + k] =
                (k <= i) ? Hmf[POS(i, k)] : Hmf[POS(k, i)];
#pragma unroll
    for (int i = 0; i < 7; i++) out[56 * Bc + b * 7 + i] = cor[i];
#pragma unroll
    for (int i = 0; i < 7; i++) out[63 * Bc + b * 7 + i] = gv[i];
#pragma unroll
    for (int i = 0; i < 7; i++) out[70 * Bc + b * 7 + i] = fric[i];
#pragma unroll
    for (int i = 0; i < 7; i++) out[77 * Bc + b * 7 + i] = ldr[i];
}

// ---------------- launch --------------------------------------------------------
extern "C" void kernel_launch(void* const* d_in, const int* in_sizes, int n_in,
                              void* d_out, int out_size)
{
    (void)in_sizes; (void)n_in; (void)out_size;
    const float* q   = (const float*)d_in[0];
    const float* qd  = (const float*)d_in[1];
    const float* qdd = (const float*)d_in[2];
    const float* W0  = (const float*)d_in[3];
    const float* b0  = (const float*)d_in[4];
    const float* W1  = (const float*)d_in[5];
    const float* b1  = (const float*)d_in[6];
    const float* W2  = (const float*)d_in[7];
    const float* b2  = (const float*)d_in[8];
    const float* Wg  = (const float*)d_in[9];
    const float* bg  = (const float*)d_in[10];
    const float* Wld = (const float*)d_in[11];
    const float* bld = (const float*)d_in[12];
    const float* Wlt = (const float*)d_in[13];
    const float* blt = (const float*)d_in[14];
    const float* fd  = (const float*)d_in[15];
    const float* fc  = (const float*)d_in[16];
    const float* fs  = (const float*)d_in[17];
    const float* fv  = (const float*)d_in[18];
    float* out = (float*)d_out;

    cudaFuncSetAttribute(k_val0,  cudaFuncAttributeMaxDynamicSharedMemorySize, VSM);
    cudaFuncSetAttribute(k_fuseA, cudaFuncAttributeMaxDynamicSharedMemorySize, VSM);
    cudaFuncSetAttribute(k_fuseB, cudaFuncAttributeMaxDynamicSharedMemorySize, VSM);
    cudaFuncSetAttribute(k_fuseC, cudaFuncAttributeMaxDynamicSharedMemorySize, TSM);
    cudaFuncSetAttribute(k_g1,    cudaFuncAttributeMaxDynamicSharedMemorySize, TSM);
    cudaFuncSetAttribute(k_g0s,   cudaFuncAttributeMaxDynamicSharedMemorySize, TSM);
    cudaFuncSetAttribute(k_sv,    cudaFuncAttributeMaxDynamicSharedMemorySize, TSM);

    k_prep <<<1344, 256>>>(q, qd, W0, b0, W1, W2,
                           Wg, bg, Wld, bld, Wlt, blt);      // h0,sg0,U0 | splits
    k_val0 <<<dim3(4, BATCH / 128), 256, VSM>>>(b1);         // h1, sig1
    k_fuseA<<<dim3(8, BATCH / 128), 256, VSM>>>(b2);         // X2,sig2 || U1
    k_fuseB<<<dim3(5, BATCH / 128), 256, VSM>>>();           // U2 || Yh 0..34
    k_fuseC<<<dim3(5, BATCH / 128), 256, TSM>>>(qd);         // G2(seeded) || Yh 35..69
    k_g1   <<<dim3(4, BATCH / 128), 256, TSM>>>();           // G1
    k_g0s  <<<dim3(4, BATCH / 128), 256, TSM>>>();           // G0s
    k_sv   <<<dim3(1, BATCH / 128), 256, TSM>>>();           // Yh 70..76
    k_dyn  <<<(BATCH + 127) / 128, 128>>>(qd, qdd, fd, fc, fs, fv, out);
}